// round 4
// baseline (speedup 1.0000x reference)
#include <cuda_runtime.h>
#include <cuda_bf16.h>

typedef unsigned long long ull;

#define B_  16
#define NPTS 4096          // N == M == 4096
#define TOTAL_PTS (B_ * NPTS)
#define CHAM_THREADS 128
#define RX 4               // queries per thread
#define QPB (CHAM_THREADS * RX)          // 512 queries per block
#define CHUNKS (NPTS / QPB)              // 8 chunks per batch per direction
#define CHAM_BLOCKS (2 * B_ * CHUNKS)    // 256 blocks
#define SMEM_BYTES (4 * NPTS * sizeof(float))  // 64 KB SoA db tile

// Scratch (no allocations allowed): packed clouds {p0,p1,p2, 0.5*|p|^2}
__device__ float4 g_X[TOTAL_PTS];   // X_v packed
__device__ float4 g_Y[TOTAL_PTS];   // rigid-transformed target packed
__device__ float  g_partial[CHAM_BLOCKS];

// ---------------- f32x2 helpers (Blackwell packed fp32) ----------------
__device__ __forceinline__ ull pack2(float a, float b) {
    ull r;
    asm("mov.b64 %0, {%1, %2};" : "=l"(r) : "f"(a), "f"(b));
    return r;
}
__device__ __forceinline__ ull fma2(ull a, ull b, ull c) {
    ull d;
    asm("fma.rn.f32x2 %0, %1, %2, %3;" : "=l"(d) : "l"(a), "l"(b), "l"(c));
    return d;
}
__device__ __forceinline__ float2 unpk(ull v) {
    float2 f;
    asm("mov.b64 {%0, %1}, %2;" : "=f"(f.x), "=f"(f.y) : "l"(v));
    return f;
}

// ---------------- Pass 1: pack X, transform+pack Y ----------------
// riged_j = v0*T[0][j] + v1*T[1][j] + v2*T[2][j] + T[3][j]  (row-vector convention),
// then divide by w (T's last column is [0,0,0,1]^T, so w == 1, but we follow the ref).
__global__ void pack_kernel(const float* __restrict__ X,
                            const float* __restrict__ TV,
                            const float* __restrict__ TR) {
    int i = blockIdx.x * blockDim.x + threadIdx.x;
    if (i < TOTAL_PTS) {
        float x0 = X[3 * i], x1 = X[3 * i + 1], x2 = X[3 * i + 2];
        g_X[i] = make_float4(x0, x1, x2, 0.5f * (x0 * x0 + x1 * x1 + x2 * x2));
    } else if (i < 2 * TOTAL_PTS) {
        int k = i - TOTAL_PTS;
        int b = k >> 12;                 // k / 4096
        float v0 = TV[3 * k], v1 = TV[3 * k + 1], v2 = TV[3 * k + 2];
        const float* Tm = TR + 16 * b;   // row-major [4][4]
        float y0 = v0 * Tm[0] + v1 * Tm[4] + v2 * Tm[8]  + Tm[12];
        float y1 = v0 * Tm[1] + v1 * Tm[5] + v2 * Tm[9]  + Tm[13];
        float y2 = v0 * Tm[2] + v1 * Tm[6] + v2 * Tm[10] + Tm[14];
        float w  = v0 * Tm[3] + v1 * Tm[7] + v2 * Tm[11] + Tm[15];
        float inv = 1.0f / w;
        y0 *= inv; y1 *= inv; y2 *= inv;
        g_Y[k] = make_float4(y0, y1, y2, 0.5f * (y0 * y0 + y1 * y1 + y2 * y2));
    }
}

// ---------------- Pass 2: chamfer, both directions in one grid ----------------
// Block: 128 threads, RX=4 queries each (512 queries), scans the full 4096-point
// database for its batch from a 64KB SoA smem tile.
// u = 0.5|y|^2 - x.y computed as fma chain; min_d = max(2*(0.5|x|^2 + min u), 0).
__global__ void __launch_bounds__(CHAM_THREADS)
chamfer_kernel() {
    extern __shared__ float sm[];
    float* s0 = sm;
    float* s1 = sm + NPTS;
    float* s2 = sm + 2 * NPTS;
    float* sh = sm + 3 * NPTS;

    int bid   = blockIdx.x;
    int dir   = bid >> 7;        // 128 blocks per direction
    int r     = bid & 127;
    int b     = r >> 3;          // 8 chunks per batch
    int chunk = r & 7;

    const float4* __restrict__ Q = (dir == 0 ? g_X : g_Y) + b * NPTS + chunk * QPB;
    const float4* __restrict__ D = (dir == 0 ? g_Y : g_X) + b * NPTS;

    int tid = threadIdx.x;
    for (int i = tid; i < NPTS; i += CHAM_THREADS) {
        float4 p = D[i];
        s0[i] = p.x; s1[i] = p.y; s2[i] = p.z; sh[i] = p.w;
    }
    __syncthreads();

    ull nx0[RX], nx1[RX], nx2[RX];
    float qw[RX];
#pragma unroll
    for (int rr = 0; rr < RX; rr++) {
        float4 q = Q[tid + rr * CHAM_THREADS];
        nx0[rr] = pack2(-q.x, -q.x);
        nx1[rr] = pack2(-q.y, -q.y);
        nx2[rr] = pack2(-q.z, -q.z);
        qw[rr]  = q.w;
    }

    // 4 independent min accumulators per query (breaks FMNMX dep chains)
    float mA[RX], mB[RX], mC[RX], mD[RX];
#pragma unroll
    for (int rr = 0; rr < RX; rr++) { mA[rr] = mB[rr] = mC[rr] = mD[rr] = 1e30f; }

#pragma unroll 2
    for (int j = 0; j < NPTS; j += 4) {
        ull p0a = *(const ull*)(s0 + j);     ull p0b = *(const ull*)(s0 + j + 2);
        ull p1a = *(const ull*)(s1 + j);     ull p1b = *(const ull*)(s1 + j + 2);
        ull p2a = *(const ull*)(s2 + j);     ull p2b = *(const ull*)(s2 + j + 2);
        ull pha = *(const ull*)(sh + j);     ull phb = *(const ull*)(sh + j + 2);
#pragma unroll
        for (int rr = 0; rr < RX; rr++) {
            ull u = fma2(nx2[rr], p2a, pha);
            u     = fma2(nx1[rr], p1a, u);
            u     = fma2(nx0[rr], p0a, u);
            float2 fu = unpk(u);
            mA[rr] = fminf(mA[rr], fu.x);
            mB[rr] = fminf(mB[rr], fu.y);

            ull v = fma2(nx2[rr], p2b, phb);
            v     = fma2(nx1[rr], p1b, v);
            v     = fma2(nx0[rr], p0b, v);
            float2 fv = unpk(v);
            mC[rr] = fminf(mC[rr], fv.x);
            mD[rr] = fminf(mD[rr], fv.y);
        }
    }

    float s = 0.0f;
#pragma unroll
    for (int rr = 0; rr < RX; rr++) {
        float m = fminf(fminf(mA[rr], mB[rr]), fminf(mC[rr], mD[rr]));
        s += fmaxf(2.0f * (qw[rr] + m), 0.0f);
    }

    __shared__ float red[CHAM_THREADS];
    red[tid] = s;
    __syncthreads();
#pragma unroll
    for (int off = CHAM_THREADS / 2; off > 0; off >>= 1) {
        if (tid < off) red[tid] += red[tid + off];
        __syncthreads();
    }
    if (tid == 0) g_partial[bid] = red[0];
}

// ---------------- Pass 3: deterministic final reduce ----------------
__global__ void finalize_kernel(float* __restrict__ out) {
    __shared__ float red[CHAM_BLOCKS];
    int t = threadIdx.x;
    red[t] = g_partial[t];
    __syncthreads();
#pragma unroll
    for (int off = CHAM_BLOCKS / 2; off > 0; off >>= 1) {
        if (t < off) red[t] += red[t + off];
        __syncthreads();
    }
    if (t == 0) out[0] = red[0];
}

extern "C" void kernel_launch(void* const* d_in, const int* in_sizes, int n_in,
                              void* d_out, int out_size) {
    const float* X  = (const float*)d_in[0];  // [16,4096,3]
    const float* TV = (const float*)d_in[1];  // [16,4096,3]
    const float* TR = (const float*)d_in[2];  // [16,4,4]
    float* out = (float*)d_out;

    cudaFuncSetAttribute(chamfer_kernel,
                         cudaFuncAttributeMaxDynamicSharedMemorySize, SMEM_BYTES);

    int total = 2 * TOTAL_PTS;
    pack_kernel<<<(total + 255) / 256, 256>>>(X, TV, TR);
    chamfer_kernel<<<CHAM_BLOCKS, CHAM_THREADS, SMEM_BYTES>>>();
    finalize_kernel<<<1, CHAM_BLOCKS>>>(out);
}

// round 5
// speedup vs baseline: 1.1812x; 1.1812x over previous
#include <cuda_runtime.h>
#include <cuda_bf16.h>

typedef unsigned long long ull;

#define B_  16
#define NPTS 4096
#define TOTAL_PTS (B_ * NPTS)            // 65536 per cloud
#define QTOT (2 * TOTAL_PTS)             // 131072 queries (both directions)
#define CHAM_THREADS 128
#define RX 4                             // queries per thread
#define QPB (CHAM_THREADS * RX)          // 512 queries per block
#define QCHUNKS (NPTS / QPB)             // 8
#define SPLIT 4                          // db split factor
#define DBT (NPTS / SPLIT)               // 1024-point db tile (16KB smem)
#define CHAM_BLOCKS (2 * B_ * QCHUNKS * SPLIT)   // 1024 blocks
#define COMB_BLOCKS 256
#define COMB_THREADS 512

// Scratch (no allocations allowed)
__device__ float4 g_X[TOTAL_PTS];        // X_v packed {x,y,z, 0.5|x|^2}
__device__ float4 g_Y[TOTAL_PTS];        // transformed target, packed
__device__ float  g_val[SPLIT * QTOT];   // per-(split, query) clamped chamfer value
__device__ float  g_cpart[COMB_BLOCKS];  // combine-stage partial sums

// ---------------- f32x2 helpers (Blackwell packed fp32 FMA) ----------------
__device__ __forceinline__ ull pack2(float a, float b) {
    ull r;
    asm("mov.b64 %0, {%1, %2};" : "=l"(r) : "f"(a), "f"(b));
    return r;
}
__device__ __forceinline__ ull fma2(ull a, ull b, ull c) {
    ull d;
    asm("fma.rn.f32x2 %0, %1, %2, %3;" : "=l"(d) : "l"(a), "l"(b), "l"(c));
    return d;
}
__device__ __forceinline__ float2 unpk(ull v) {
    float2 f;
    asm("mov.b64 {%0, %1}, %2;" : "=f"(f.x), "=f"(f.y) : "l"(v));
    return f;
}

// ---------------- Pass 1: pack X, transform+pack Y (4 pts / thread) ----------------
__global__ void pack_kernel(const float* __restrict__ X,
                            const float* __restrict__ TV,
                            const float* __restrict__ TR) {
    const int groups = TOTAL_PTS / 4;    // 16384 float4-triples per cloud
    int t = blockIdx.x * blockDim.x + threadIdx.x;

    if (t < groups) {
        const float4* src = (const float4*)X + 3 * t;
        float4 A = src[0], Bv = src[1], C = src[2];
        float c[12] = {A.x, A.y, A.z, A.w, Bv.x, Bv.y, Bv.z, Bv.w, C.x, C.y, C.z, C.w};
#pragma unroll
        for (int p = 0; p < 4; p++) {
            float x0 = c[3 * p], x1 = c[3 * p + 1], x2 = c[3 * p + 2];
            g_X[4 * t + p] = make_float4(x0, x1, x2,
                                         0.5f * (x0 * x0 + x1 * x1 + x2 * x2));
        }
    } else if (t < 2 * groups) {
        int k = t - groups;                       // float4-triple index in target cloud
        const float4* src = (const float4*)TV + 3 * k;
        float4 A = src[0], Bv = src[1], C = src[2];
        float c[12] = {A.x, A.y, A.z, A.w, Bv.x, Bv.y, Bv.z, Bv.w, C.x, C.y, C.z, C.w};
        int b = (4 * k) >> 12;                    // batch (groups never cross batches)
        const float4* Tm = (const float4*)(TR + 16 * b);  // rows of [4][4]
        float4 T0 = Tm[0], T1 = Tm[1], T2 = Tm[2], T3 = Tm[3];
#pragma unroll
        for (int p = 0; p < 4; p++) {
            float v0 = c[3 * p], v1 = c[3 * p + 1], v2 = c[3 * p + 2];
            // row-vector convention: y_j = v0*T[0][j] + v1*T[1][j] + v2*T[2][j] + T[3][j]
            float y0 = v0 * T0.x + v1 * T1.x + v2 * T2.x + T3.x;
            float y1 = v0 * T0.y + v1 * T1.y + v2 * T2.y + T3.y;
            float y2 = v0 * T0.z + v1 * T1.z + v2 * T2.z + T3.z;
            float w  = v0 * T0.w + v1 * T1.w + v2 * T2.w + T3.w;
            float inv = 1.0f / w;
            y0 *= inv; y1 *= inv; y2 *= inv;
            g_Y[4 * k + p] = make_float4(y0, y1, y2,
                                         0.5f * (y0 * y0 + y1 * y1 + y2 * y2));
        }
    }
}

// ---------------- Pass 2: chamfer over a db SPLIT tile ----------------
// bid decodes (dir, batch, query-chunk, split). Block loads a 1024-pt db tile
// into SoA smem, computes per-query min over that tile, and stores the clamped
// affine value max(2*(qw + min_u), 0) — clamp & affine are monotone, so they
// commute with the min-over-splits done in the combine pass.
__global__ void __launch_bounds__(CHAM_THREADS)
chamfer_kernel() {
    __shared__ float sm[4 * DBT];        // 16 KB SoA tile
    float* s0 = sm;
    float* s1 = sm + DBT;
    float* s2 = sm + 2 * DBT;
    float* sh = sm + 3 * DBT;

    int bid   = blockIdx.x;
    int split = bid & (SPLIT - 1);
    int g     = bid >> 2;                // 0..255 : dir*128 + b*8 + qc
    int qc    = g & 7;
    int b     = (g >> 3) & 15;
    int dir   = g >> 7;

    const float4* __restrict__ Q = (dir == 0 ? g_X : g_Y) + b * NPTS + qc * QPB;
    const float4* __restrict__ D = (dir == 0 ? g_Y : g_X) + b * NPTS + split * DBT;

    int tid = threadIdx.x;
    for (int i = tid; i < DBT; i += CHAM_THREADS) {
        float4 p = D[i];
        s0[i] = p.x; s1[i] = p.y; s2[i] = p.z; sh[i] = p.w;
    }
    __syncthreads();

    ull nx0[RX], nx1[RX], nx2[RX];
    float qw[RX];
#pragma unroll
    for (int rr = 0; rr < RX; rr++) {
        float4 q = Q[tid + rr * CHAM_THREADS];
        nx0[rr] = pack2(-q.x, -q.x);
        nx1[rr] = pack2(-q.y, -q.y);
        nx2[rr] = pack2(-q.z, -q.z);
        qw[rr]  = q.w;
    }

    float mA[RX], mB[RX], mC[RX], mD[RX];
#pragma unroll
    for (int rr = 0; rr < RX; rr++) { mA[rr] = mB[rr] = mC[rr] = mD[rr] = 1e30f; }

#pragma unroll 4
    for (int j = 0; j < DBT; j += 4) {
        ull p0a = *(const ull*)(s0 + j);   ull p0b = *(const ull*)(s0 + j + 2);
        ull p1a = *(const ull*)(s1 + j);   ull p1b = *(const ull*)(s1 + j + 2);
        ull p2a = *(const ull*)(s2 + j);   ull p2b = *(const ull*)(s2 + j + 2);
        ull pha = *(const ull*)(sh + j);   ull phb = *(const ull*)(sh + j + 2);
#pragma unroll
        for (int rr = 0; rr < RX; rr++) {
            // u = 0.5|y|^2 - x.y  (3-FMA chain per packed pair)
            ull u = fma2(nx2[rr], p2a, pha);
            u     = fma2(nx1[rr], p1a, u);
            u     = fma2(nx0[rr], p0a, u);
            float2 fu = unpk(u);
            mA[rr] = fminf(mA[rr], fu.x);
            mB[rr] = fminf(mB[rr], fu.y);

            ull v = fma2(nx2[rr], p2b, phb);
            v     = fma2(nx1[rr], p1b, v);
            v     = fma2(nx0[rr], p0b, v);
            float2 fv = unpk(v);
            mC[rr] = fminf(mC[rr], fv.x);
            mD[rr] = fminf(mD[rr], fv.y);
        }
    }

    int qbase = g * QPB;                 // global query index base (dir folded in)
#pragma unroll
    for (int rr = 0; rr < RX; rr++) {
        float m = fminf(fminf(mA[rr], mB[rr]), fminf(mC[rr], mD[rr]));
        float val = fmaxf(2.0f * (qw[rr] + m), 0.0f);
        g_val[split * QTOT + qbase + tid + rr * CHAM_THREADS] = val;
    }
}

// ---------------- Pass 3: min over splits + deterministic block sums ----------------
__global__ void __launch_bounds__(COMB_THREADS)
combine_kernel() {
    int q = blockIdx.x * COMB_THREADS + threadIdx.x;
    float v = fminf(fminf(g_val[q],            g_val[QTOT + q]),
                    fminf(g_val[2 * QTOT + q], g_val[3 * QTOT + q]));

    __shared__ float red[COMB_THREADS];
    int t = threadIdx.x;
    red[t] = v;
    __syncthreads();
#pragma unroll
    for (int off = COMB_THREADS / 2; off > 0; off >>= 1) {
        if (t < off) red[t] += red[t + off];
        __syncthreads();
    }
    if (t == 0) g_cpart[blockIdx.x] = red[0];
}

// ---------------- Pass 4: deterministic final reduce ----------------
__global__ void finalize_kernel(float* __restrict__ out) {
    __shared__ float red[COMB_BLOCKS];
    int t = threadIdx.x;
    red[t] = g_cpart[t];
    __syncthreads();
#pragma unroll
    for (int off = COMB_BLOCKS / 2; off > 0; off >>= 1) {
        if (t < off) red[t] += red[t + off];
        __syncthreads();
    }
    if (t == 0) out[0] = red[0];
}

extern "C" void kernel_launch(void* const* d_in, const int* in_sizes, int n_in,
                              void* d_out, int out_size) {
    const float* X  = (const float*)d_in[0];  // [16,4096,3]
    const float* TV = (const float*)d_in[1];  // [16,4096,3]
    const float* TR = (const float*)d_in[2];  // [16,4,4]
    float* out = (float*)d_out;

    int pack_threads = 2 * (TOTAL_PTS / 4);   // 32768
    pack_kernel<<<pack_threads / 256, 256>>>(X, TV, TR);
    chamfer_kernel<<<CHAM_BLOCKS, CHAM_THREADS>>>();
    combine_kernel<<<COMB_BLOCKS, COMB_THREADS>>>();
    finalize_kernel<<<1, COMB_BLOCKS>>>(out);
}

// round 6
// speedup vs baseline: 1.2441x; 1.0533x over previous
#include <cuda_runtime.h>
#include <cuda_bf16.h>

typedef unsigned long long ull;

#define B_  16
#define NPTS 4096
#define TOTAL_PTS (B_ * NPTS)            // 65536 per cloud
#define QTOT (2 * TOTAL_PTS)             // 131072 queries (both directions)
#define CHAM_THREADS 128
#define RX 8                             // queries per thread
#define QPB (CHAM_THREADS * RX)          // 1024 queries per block
#define QCHUNKS (NPTS / QPB)             // 4
#define SPLIT 8                          // db split factor
#define DBT (NPTS / SPLIT)               // 512-point db tile (8KB smem)
#define CHAM_BLOCKS (2 * B_ * QCHUNKS * SPLIT)   // 1024 blocks
#define COMB_BLOCKS 256
#define COMB_THREADS 512

// Scratch (no device allocations allowed)
__device__ float g_val[SPLIT * QTOT];    // per-(split, query) clamped chamfer value
__device__ float g_cpart[COMB_BLOCKS];

// ---------------- f32x2 helpers (Blackwell packed fp32 FMA) ----------------
__device__ __forceinline__ ull pack2(float a, float b) {
    ull r;
    asm("mov.b64 %0, {%1, %2};" : "=l"(r) : "f"(a), "f"(b));
    return r;
}
__device__ __forceinline__ ull fma2(ull a, ull b, ull c) {
    ull d;
    asm("fma.rn.f32x2 %0, %1, %2, %3;" : "=l"(d) : "l"(a), "l"(b), "l"(c));
    return d;
}
__device__ __forceinline__ float2 unpk(ull v) {
    float2 f;
    asm("mov.b64 {%0, %1}, %2;" : "=f"(f.x), "=f"(f.y) : "l"(v));
    return f;
}

// ---------------- Pass 1: fused transform + chamfer over a db split tile ----------
// bid -> (dir, batch, query-chunk, split). The block transforms/packs its own
// 512-pt db tile into SoA smem and its 1024 queries into registers, then scans.
// Stores max(2*(qw + min_u), 0) per (query, split); clamp & affine are monotone
// so they commute with the min-over-splits in the combine pass.
__global__ void __launch_bounds__(CHAM_THREADS, 4)
chamfer_kernel(const float* __restrict__ X,
               const float* __restrict__ TV,
               const float* __restrict__ TR) {
    __shared__ __align__(16) float s0[DBT];
    __shared__ __align__(16) float s1[DBT];
    __shared__ __align__(16) float s2[DBT];
    __shared__ __align__(16) float sh[DBT];

    int bid   = blockIdx.x;
    int split = bid & (SPLIT - 1);
    int g     = bid >> 3;                 // 0..127 : dir*64 + b*4 + qc
    int qc    = g & (QCHUNKS - 1);
    int b     = (g >> 2) & 15;
    int dir   = g >> 6;
    int tid   = threadIdx.x;

    // Batch transform matrix (row-major [4][4], row-vector convention)
    const float* Tm = TR + 16 * b;
    float T00 = __ldg(Tm + 0),  T01 = __ldg(Tm + 1),  T02 = __ldg(Tm + 2),  T03 = __ldg(Tm + 3);
    float T10 = __ldg(Tm + 4),  T11 = __ldg(Tm + 5),  T12 = __ldg(Tm + 6),  T13 = __ldg(Tm + 7);
    float T20 = __ldg(Tm + 8),  T21 = __ldg(Tm + 9),  T22 = __ldg(Tm + 10), T23 = __ldg(Tm + 11);
    float T30 = __ldg(Tm + 12), T31 = __ldg(Tm + 13), T32 = __ldg(Tm + 14), T33 = __ldg(Tm + 15);

    // Database tile: dir==0 -> transformed target, dir==1 -> X
    const float* Draw = (dir == 0 ? TV : X) + (size_t)(b * NPTS + split * DBT) * 3;
#pragma unroll
    for (int i = tid; i < DBT; i += CHAM_THREADS) {
        float v0 = Draw[3 * i], v1 = Draw[3 * i + 1], v2 = Draw[3 * i + 2];
        float y0, y1, y2;
        if (dir == 0) {
            y0 = v0 * T00 + v1 * T10 + v2 * T20 + T30;
            y1 = v0 * T01 + v1 * T11 + v2 * T21 + T31;
            y2 = v0 * T02 + v1 * T12 + v2 * T22 + T32;
            float w = v0 * T03 + v1 * T13 + v2 * T23 + T33;
            float inv = 1.0f / w;
            y0 *= inv; y1 *= inv; y2 *= inv;
        } else {
            y0 = v0; y1 = v1; y2 = v2;
        }
        s0[i] = y0; s1[i] = y1; s2[i] = y2;
        sh[i] = 0.5f * (y0 * y0 + y1 * y1 + y2 * y2);
    }

    // Queries: dir==0 -> X, dir==1 -> transformed target
    const float* Qraw = (dir == 0 ? X : TV) + (size_t)(b * NPTS + qc * QPB) * 3;
    ull nx0[RX], nx1[RX], nx2[RX];
    float qw[RX];
#pragma unroll
    for (int rr = 0; rr < RX; rr++) {
        int idx = tid + rr * CHAM_THREADS;
        float v0 = Qraw[3 * idx], v1 = Qraw[3 * idx + 1], v2 = Qraw[3 * idx + 2];
        float y0, y1, y2;
        if (dir == 1) {
            y0 = v0 * T00 + v1 * T10 + v2 * T20 + T30;
            y1 = v0 * T01 + v1 * T11 + v2 * T21 + T31;
            y2 = v0 * T02 + v1 * T12 + v2 * T22 + T32;
            float w = v0 * T03 + v1 * T13 + v2 * T23 + T33;
            float inv = 1.0f / w;
            y0 *= inv; y1 *= inv; y2 *= inv;
        } else {
            y0 = v0; y1 = v1; y2 = v2;
        }
        nx0[rr] = pack2(-y0, -y0);
        nx1[rr] = pack2(-y1, -y1);
        nx2[rr] = pack2(-y2, -y2);
        qw[rr]  = 0.5f * (y0 * y0 + y1 * y1 + y2 * y2);
    }
    __syncthreads();

    float m0[RX], m1[RX];
#pragma unroll
    for (int rr = 0; rr < RX; rr++) { m0[rr] = 1e30f; m1[rr] = 1e30f; }

    // Main scan: 4 db points per group via LDS.128 (ulonglong2), 3-FMA2 chain each
#pragma unroll 2
    for (int j = 0; j < DBT; j += 4) {
        ulonglong2 L0 = *(const ulonglong2*)(s0 + j);
        ulonglong2 L1 = *(const ulonglong2*)(s1 + j);
        ulonglong2 L2 = *(const ulonglong2*)(s2 + j);
        ulonglong2 LH = *(const ulonglong2*)(sh + j);
#pragma unroll
        for (int rr = 0; rr < RX; rr++) {
            // u = 0.5|y|^2 - x.y
            ull u = fma2(nx2[rr], L2.x, LH.x);
            u     = fma2(nx1[rr], L1.x, u);
            u     = fma2(nx0[rr], L0.x, u);
            float2 fu = unpk(u);
            m0[rr] = fminf(m0[rr], fu.x);
            m1[rr] = fminf(m1[rr], fu.y);

            ull v = fma2(nx2[rr], L2.y, LH.y);
            v     = fma2(nx1[rr], L1.y, v);
            v     = fma2(nx0[rr], L0.y, v);
            float2 fv = unpk(v);
            m0[rr] = fminf(m0[rr], fv.x);
            m1[rr] = fminf(m1[rr], fv.y);
        }
    }

    int qbase = g * QPB;
#pragma unroll
    for (int rr = 0; rr < RX; rr++) {
        float m = fminf(m0[rr], m1[rr]);
        float val = fmaxf(2.0f * (qw[rr] + m), 0.0f);
        g_val[(size_t)split * QTOT + qbase + tid + rr * CHAM_THREADS] = val;
    }
}

// ---------------- Pass 2: min over splits + deterministic block sums ----------------
__global__ void __launch_bounds__(COMB_THREADS)
combine_kernel() {
    int q = blockIdx.x * COMB_THREADS + threadIdx.x;
    float v = g_val[q];
#pragma unroll
    for (int k = 1; k < SPLIT; k++)
        v = fminf(v, g_val[(size_t)k * QTOT + q]);

    __shared__ float red[COMB_THREADS];
    int t = threadIdx.x;
    red[t] = v;
    __syncthreads();
#pragma unroll
    for (int off = COMB_THREADS / 2; off > 0; off >>= 1) {
        if (t < off) red[t] += red[t + off];
        __syncthreads();
    }
    if (t == 0) g_cpart[blockIdx.x] = red[0];
}

// ---------------- Pass 3: deterministic final reduce ----------------
__global__ void finalize_kernel(float* __restrict__ out) {
    __shared__ float red[COMB_BLOCKS];
    int t = threadIdx.x;
    red[t] = g_cpart[t];
    __syncthreads();
#pragma unroll
    for (int off = COMB_BLOCKS / 2; off > 0; off >>= 1) {
        if (t < off) red[t] += red[t + off];
        __syncthreads();
    }
    if (t == 0) out[0] = red[0];
}

extern "C" void kernel_launch(void* const* d_in, const int* in_sizes, int n_in,
                              void* d_out, int out_size) {
    const float* X  = (const float*)d_in[0];  // [16,4096,3]
    const float* TV = (const float*)d_in[1];  // [16,4096,3]
    const float* TR = (const float*)d_in[2];  // [16,4,4]
    float* out = (float*)d_out;

    chamfer_kernel<<<CHAM_BLOCKS, CHAM_THREADS>>>(X, TV, TR);
    combine_kernel<<<COMB_BLOCKS, COMB_THREADS>>>();
    finalize_kernel<<<1, COMB_BLOCKS>>>(out);
}